// round 16
// baseline (speedup 1.0000x reference)
#include <cuda_runtime.h>
#include <cuda_bf16.h>
#include <cuda_fp16.h>
#include <cstdint>

// Problem constants
#define B_    256
#define T_    512
#define EMB_  512
#define HID_  1024
#define HEAD_ 100
#define NCLS_ 10
#define VOC_  32000
#define BH    (B_*HID_)

#define MTILES 250            // vocab tiles (m)
#define NTILES 8              // hidden column tiles (n)
#define NPREP_A 250           // A-split CTAs
#define NPREP_U 8             // U-split CTAs
#define NPREP_W 16            // W-check CTAs
#define NPREP  (NPREP_A + NPREP_U + NPREP_W)      // 274
#define NGEMM  (MTILES*NTILES)                    // 2000
#define NREC   128
#define NCTAS  (NPREP + NGEMM + NREC)             // 2402

// ---------------- static device scratch -------------------------------------
__device__ __half g_projh[(size_t)VOC_*HID_];   // emb @ U^T in fp16, 66 MB
__device__ __half g_Ah[(size_t)VOC_*EMB_];      // emb fp16 (rounded once)
__device__ __half g_Bh[HID_*EMB_];              // U fp16 (rounded once)
__device__ float  g_h [BH];
__device__ float  g_h2[BH];
__device__ float  g_wdiag[HID_];
__device__ int    g_flag;
__device__ unsigned g_maxw_bits;                // max |wdiag| as positive-float bits
__device__ unsigned g_barcnt;
__device__ unsigned g_cnt[NTILES];              // per-column-tile GEMM completion
__device__ unsigned g_asplit[NPREP_A];          // per-m-tile A split done
__device__ unsigned g_usplit[NTILES];           // per-n-tile U split done
__device__ unsigned g_chkcnt;                   // W-check slices done (16)

// ---------------- init -------------------------------------------------------
__global__ void k_init() {
    int t = threadIdx.x;
    if (t == 0) { g_flag = 1; g_maxw_bits = 0u; g_barcnt = 0u; g_chkcnt = 0u; }
    for (int i = t; i < NPREP_A; i += blockDim.x) g_asplit[i] = 0u;
    if (t < NTILES) { g_usplit[t] = 0u; g_cnt[t] = 0u; }
}

// ---------------- mma/ldsm/cp.async helpers ----------------------------------
__device__ __forceinline__ void ldsm4(unsigned& r0, unsigned& r1,
                                      unsigned& r2, unsigned& r3, unsigned addr) {
    asm volatile("ldmatrix.sync.aligned.m8n8.x4.shared.b16 {%0,%1,%2,%3},[%4];\n"
                 : "=r"(r0), "=r"(r1), "=r"(r2), "=r"(r3) : "r"(addr));
}
__device__ __forceinline__ void mma_f16(float* c, const unsigned* a, const unsigned* b) {
    asm volatile(
        "mma.sync.aligned.m16n8k16.row.col.f32.f16.f16.f32 "
        "{%0,%1,%2,%3},{%4,%5,%6,%7},{%8,%9},{%0,%1,%2,%3};\n"
        : "+f"(c[0]), "+f"(c[1]), "+f"(c[2]), "+f"(c[3])
        : "r"(a[0]), "r"(a[1]), "r"(a[2]), "r"(a[3]), "r"(b[0]), "r"(b[1]));
}
__device__ __forceinline__ void cp16(unsigned dst, const void* src) {
    asm volatile("cp.async.cg.shared.global [%0], [%1], 16;\n" :: "r"(dst), "l"(src) : "memory");
}
__device__ __forceinline__ void cp_commit() {
    asm volatile("cp.async.commit_group;\n" ::: "memory");
}
template<int N> __device__ __forceinline__ void cp_wait() {
    asm volatile("cp.async.wait_group %0;\n" :: "n"(N) : "memory");
}
__device__ __forceinline__ void cvt_store4(__half* dst, float4 v) {
    __half h[4];
    h[0] = __float2half_rn(v.x); h[1] = __float2half_rn(v.y);
    h[2] = __float2half_rn(v.z); h[3] = __float2half_rn(v.w);
    *reinterpret_cast<uint2*>(dst) =
        make_uint2((unsigned)__half_as_ushort(h[0]) | ((unsigned)__half_as_ushort(h[1]) << 16),
                   (unsigned)__half_as_ushort(h[2]) | ((unsigned)__half_as_ushort(h[3]) << 16));
}

// GEMM geometry (R12/R15 best): CTA 128x128, 8 warps (2m x 4n), warp 64x32,
// BK=32 (two k16 subs), 3-stage cp.async pipeline, occ 2.
#define SMS 24                                   // smem row stride in fp16 elems
#define SUB_BYTES (128*SMS*2)                    // 6144 B per tensor per k16 sub
#define STG_BYTES (4*SUB_BYTES)                  // A0,A1,B0,B1 = 24576 B
#define NSTG 3
#define SMEM_TOTAL (NSTG*STG_BYTES)              // 73728 B; x2 CTAs = 144 KB/SM
#define NIT (EMB_/32)                            // 16 stages

// Mega kernel: [0,250) A-split | [250,258) U-split | [258,274) W-check |
//              [274,2274) GEMM | [2274,2402) truncated recurrence.
__global__ void __launch_bounds__(256, 2)
k_mega(const float* __restrict__ emb, const float* __restrict__ U,
       const float* __restrict__ W, const int* __restrict__ ids,
       const float* __restrict__ Wb) {
    extern __shared__ __align__(16) char smem_dyn[];
    const int bid = blockIdx.x;
    const int tid = threadIdx.x;

    if (bid < NPREP_A) {
        // ---------- A split: m-tile bid, 128 rows x 512 = 16384 float4 ----------
        const int p = bid;
        const float4* src = reinterpret_cast<const float4*>(emb) + (size_t)p * 16384;
        __half* dst = g_Ah + (size_t)p * 65536;
#pragma unroll 4
        for (int i = tid; i < 16384; i += 256)
            cvt_store4(dst + 4*(size_t)i, __ldg(src + i));
        __threadfence();
        __syncthreads();
        if (tid == 0) atomicExch(&g_asplit[p], 1u);

    } else if (bid < NPREP_A + NPREP_U) {
        // ---------- U split: n-tile, 128 rows x 512 = 16384 float4 ----------
        const int p = bid - NPREP_A;
        const float4* src = reinterpret_cast<const float4*>(U) + (size_t)p * 16384;
        __half* dst = g_Bh + (size_t)p * 65536;
#pragma unroll 4
        for (int i = tid; i < 16384; i += 256)
            cvt_store4(dst + 4*(size_t)i, __ldg(src + i));
        __threadfence();
        __syncthreads();
        if (tid == 0) atomicExch(&g_usplit[p], 1u);

    } else if (bid < NPREP) {
        // ---------- W check: 64 rows per CTA ----------
        const int c = bid - NPREP_A - NPREP_U;      // 0..15
        for (int row = c * 64; row < c * 64 + 64; ++row) {
            float4 v = __ldg(reinterpret_cast<const float4*>(W + (size_t)row * HID_) + tid);
            float vv[4] = {v.x, v.y, v.z, v.w};
#pragma unroll
            for (int p = 0; p < 4; p++) {
                int col = tid * 4 + p;
                if (col == row) {
                    g_wdiag[row] = vv[p];
                    atomicMax(&g_maxw_bits, (unsigned)__float_as_int(fabsf(vv[p])));
                } else if (vv[p] != 0.0f) g_flag = 0;
            }
        }
        __threadfence();
        __syncthreads();
        if (tid == 0) atomicAdd(&g_chkcnt, 1u);

    } else if (bid < NPREP + NGEMM) {
        // ================= GEMM part =================
        const unsigned sb = (unsigned)__cvta_generic_to_shared(smem_dyn);
        const int idx = bid - NPREP;
        const int mt = idx % MTILES, nt = idx / MTILES;   // m-fast raster
        const int m0 = mt * 128, n0 = nt * 128;

        // wait for this tile's operands to be split
        if (tid == 0) {
            while (atomicAdd(&g_asplit[mt], 0u) == 0u) __nanosleep(100);
            while (atomicAdd(&g_usplit[nt], 0u) == 0u) __nanosleep(100);
            __threadfence();
        }
        __syncthreads();

        const int r = tid >> 1, q = tid & 1;
        const unsigned doff = (unsigned)(r * SMS + q * 8) * 2;
        const __half* a_h = g_Ah + (size_t)(m0 + r) * EMB_ + q * 8;
        const __half* b_h = g_Bh + (size_t)(n0 + r) * EMB_ + q * 8;

        const int lane = tid & 31, warp = tid >> 5;
        const int wm = warp >> 2, wn = warp & 3;

        float acc[4][4][4];
#pragma unroll
        for (int i = 0; i < 4; i++)
#pragma unroll
            for (int j = 0; j < 4; j++)
#pragma unroll
                for (int k = 0; k < 4; k++) acc[i][j][k] = 0.0f;

        auto load_stage = [&](int s, int c) {
            unsigned base = sb + s * STG_BYTES + doff;
            const int k0 = c * 32;
            cp16(base,               a_h + k0);
            cp16(base + 1*SUB_BYTES, a_h + k0 + 16);
            cp16(base + 2*SUB_BYTES, b_h + k0);
            cp16(base + 3*SUB_BYTES, b_h + k0 + 16);
            cp_commit();
        };

        load_stage(0, 0);
        load_stage(1, 1);

        const int aoff0 = ((wm * 64 + (lane & 15)) * SMS + (lane >> 4) * 8) * 2;
        const int boff0 = ((wn * 32 + (lane & 7) + ((lane >> 4) << 3)) * SMS
                           + ((lane >> 3) & 1) * 8) * 2;

        for (int it = 0; it < NIT; ++it) {
            if (it < NIT-1) cp_wait<1>(); else cp_wait<0>();
            __syncthreads();
            if (it + 2 < NIT) load_stage((it + 2) % NSTG, it + 2);

            const unsigned stg = sb + (it % NSTG) * STG_BYTES;
#pragma unroll
            for (int sub = 0; sub < 2; ++sub) {
                const unsigned base = stg + sub * SUB_BYTES;
                unsigned Ah[4][4], Bh[4][2];
#pragma unroll
                for (int mi = 0; mi < 4; mi++) {
                    unsigned ad = base + aoff0 + mi * 16 * SMS * 2;
                    ldsm4(Ah[mi][0], Ah[mi][1], Ah[mi][2], Ah[mi][3], ad);
                }
#pragma unroll
                for (int p = 0; p < 2; p++) {
                    unsigned bd = base + 2*SUB_BYTES + boff0 + p * 16 * SMS * 2;
                    ldsm4(Bh[2*p][0], Bh[2*p][1], Bh[2*p+1][0], Bh[2*p+1][1], bd);
                }
#pragma unroll
                for (int mi = 0; mi < 4; mi++)
#pragma unroll
                    for (int ni = 0; ni < 4; ni++)
                        mma_f16(acc[mi][ni], Ah[mi], Bh[ni]);
            }
        }

        // epilogue: fp32 accumulators -> fp16 g_projh
#pragma unroll
        for (int mi = 0; mi < 4; mi++) {
            int mrow = m0 + wm * 64 + mi * 16 + (lane >> 2);
#pragma unroll
            for (int ni = 0; ni < 4; ni++) {
                int h = n0 + wn * 32 + ni * 8 + (lane & 3) * 2;
                *reinterpret_cast<__half2*>(&g_projh[(size_t)mrow * HID_ + h]) =
                    __floats2half2_rn(acc[mi][ni][0], acc[mi][ni][1]);
                *reinterpret_cast<__half2*>(&g_projh[(size_t)(mrow + 8) * HID_ + h]) =
                    __floats2half2_rn(acc[mi][ni][2], acc[mi][ni][3]);
            }
        }

        __threadfence();
        __syncthreads();
        if (tid == 0) atomicAdd(&g_cnt[nt], 1u);

    } else {
        // ========== truncated recurrence (diagonal fast path) ==========
        const int rb  = bid - NPREP - NGEMM;     // 0..127
        const int nt  = rb >> 4;                 // column tile 0..7
        const int sub = rb & 15;
        const int b   = sub * 16 + (tid >> 4);   // batch 0..255
        const int h8  = nt * 128 + (tid & 15) * 8;

        // wait for W-check and this column tile
        if (tid == 0) {
            while (atomicAdd(&g_chkcnt, 0u) < (unsigned)NPREP_W) __nanosleep(100);
            while (atomicAdd(&g_cnt[nt], 0u) < (unsigned)MTILES) __nanosleep(200);
            __threadfence();
        }
        __syncthreads();
        if (!g_flag) return;                     // fallback kernel handles it

        // safe truncation horizon: influence of h_{T-K} on h_T <= max|w|^K.
        const float mw = __int_as_float((int)g_maxw_bits);
        int K = T_;
        if (mw < 0.999f) {
            float l2 = log2f(fmaxf(mw, 1e-30f));
            K = (int)ceilf(-40.0f / l2);
            if (K < 1) K = 1;
            if (K > T_) K = T_;
        }
        const int t0 = T_ - K;

        float w[8], bb[8], hv[8];
#pragma unroll
        for (int p = 0; p < 8; p++) {
            w[p]  = g_wdiag[h8 + p];
            bb[p] = __ldg(&Wb[h8 + p]);
            hv[p] = 0.0f;
        }
        const int* idrow = ids + b * T_;
        for (int t = t0; t < T_; ++t) {
            int id = __ldg(&idrow[t]);
            uint4 raw = *reinterpret_cast<const uint4*>(&g_projh[(size_t)id * HID_ + h8]);
            unsigned rr[4] = {raw.x, raw.y, raw.z, raw.w};
#pragma unroll
            for (int p = 0; p < 4; p++) {
                float2 ux = __half22float2(*reinterpret_cast<const __half2*>(&rr[p]));
                hv[2*p]   = fmaxf(fmaf(hv[2*p],   w[2*p],   bb[2*p]   + ux.x), 0.f);
                hv[2*p+1] = fmaxf(fmaf(hv[2*p+1], w[2*p+1], bb[2*p+1] + ux.y), 0.f);
            }
        }
        float4* dst = reinterpret_cast<float4*>(&g_h[((size_t)b << 10) + h8]);
        dst[0] = make_float4(hv[0], hv[1], hv[2], hv[3]);
        dst[1] = make_float4(hv[4], hv[5], hv[6], hv[7]);
    }
}

// ---------------- recurrence, generic fallback (dormant in practice) --------
__global__ void k_rec_fb(const int* __restrict__ ids,
                         const float* __restrict__ W, const float* __restrict__ Wb) {
    if (g_flag) return;
    const int tid = blockIdx.x * blockDim.x + threadIdx.x;
    const int NT = gridDim.x * blockDim.x;
    for (int t = 0; t < T_; ++t) {
        const float* cur = (t & 1) ? g_h2 : g_h;
        float*       nxt = (t & 1) ? g_h  : g_h2;
        for (int o = tid; o < BH; o += NT) {
            int b = o >> 10, i = o & 1023;
            int id = ids[b * T_ + t];
            float s = Wb[i] + __half2float(g_projh[(size_t)id * HID_ + i]);
            if (t > 0) {
                const float* hr = cur + (b << 10);
                const float* wr = W + ((size_t)i << 10);
                for (int j = 0; j < HID_; ++j) s += hr[j] * wr[j];
            }
            nxt[o] = fmaxf(s, 0.0f);
        }
        __syncthreads();
        if (threadIdx.x == 0) {
            __threadfence();
            atomicAdd(&g_barcnt, 1u);
            while (atomicAdd(&g_barcnt, 0u) < 148u * (unsigned)(t + 1)) {}
        }
        __syncthreads();
    }
}

// ---------------- head ------------------------------------------------------
__global__ void k_head(const float* __restrict__ h1w, const float* __restrict__ h1b,
                       const float* __restrict__ h2w, const float* __restrict__ h2b,
                       float* __restrict__ out) {
    __shared__ float hs[HID_];
    __shared__ float zs[HEAD_];
    const int b = blockIdx.x, tid = threadIdx.x;
    const float* hrow = g_h + (size_t)b * HID_;
    for (int k = tid; k < HID_; k += 128) hs[k] = hrow[k];
    __syncthreads();

    const int warp = tid >> 5, lane = tid & 31;
    for (int j = warp; j < HEAD_; j += 4) {
        float s = 0.0f;
        const float* w = h1w + (size_t)j * HID_;
        for (int k = lane; k < HID_; k += 32) s += hs[k] * w[k];
#pragma unroll
        for (int o = 16; o; o >>= 1) s += __shfl_xor_sync(0xffffffffu, s, o);
        if (lane == 0) zs[j] = fmaxf(s + h1b[j], 0.0f);
    }
    __syncthreads();

    for (int c = warp; c < NCLS_; c += 4) {
        float s = 0.0f;
        const float* w = h2w + (size_t)c * HEAD_;
        for (int j = lane; j < HEAD_; j += 32) s += zs[j] * w[j];
#pragma unroll
        for (int o = 16; o; o >>= 1) s += __shfl_xor_sync(0xffffffffu, s, o);
        if (lane == 0) out[b * NCLS_ + c] = s + h2b[c];
    }
}

// ---------------- launcher ---------------------------------------------------
extern "C" void kernel_launch(void* const* d_in, const int* in_sizes, int n_in,
                              void* d_out, int out_size) {
    const int*   ids = (const int*)  d_in[0];
    const float* emb = (const float*)d_in[1];
    const float* U   = (const float*)d_in[2];
    const float* W   = (const float*)d_in[3];
    const float* Wb  = (const float*)d_in[4];
    const float* h1w = (const float*)d_in[5];
    const float* h1b = (const float*)d_in[6];
    const float* h2w = (const float*)d_in[7];
    const float* h2b = (const float*)d_in[8];
    float* out = (float*)d_out;

    cudaFuncSetAttribute(k_mega, cudaFuncAttributeMaxDynamicSharedMemorySize, SMEM_TOTAL);

    k_init<<<1, 256>>>();
    k_mega<<<NCTAS, 256, SMEM_TOTAL>>>(emb, U, W, ids, Wb);
    k_rec_fb<<<148, 256>>>(ids, W, Wb);
    k_head<<<B_, 128>>>(h1w, h1b, h2w, h2b, out);
}

// round 17
// speedup vs baseline: 1.1872x; 1.1872x over previous
#include <cuda_runtime.h>
#include <cuda_bf16.h>
#include <cuda_fp16.h>
#include <cstdint>

// Problem constants
#define B_    256
#define T_    512
#define EMB_  512
#define HID_  1024
#define HEAD_ 100
#define NCLS_ 10
#define VOC_  32000
#define BH    (B_*HID_)

#define MTILES 250            // vocab tiles (m)
#define NTILES 8              // hidden column tiles (n)
#define NPREP_A 250           // A-split CTAs
#define NPREP_U 8             // U-split CTAs
#define NPREP_W 16            // W-check CTAs
#define NPREP  (NPREP_A + NPREP_U + NPREP_W)      // 274
#define NGEMM  (MTILES*NTILES)                    // 2000
#define NREC   128
#define NCTAS  (NPREP + NGEMM + NREC)             // 2402

// ---------------- static device scratch -------------------------------------
__device__ __half g_projh[(size_t)VOC_*HID_];   // emb @ U^T in fp16, 66 MB
__device__ __half g_Ah[(size_t)VOC_*EMB_];      // emb fp16 (rounded once)
__device__ __half g_Bh[HID_*EMB_];              // U fp16 (rounded once)
__device__ float  g_h [BH];
__device__ float  g_h2[BH];
__device__ float  g_wdiag[HID_];
__device__ int    g_flag;
__device__ unsigned g_maxw_bits;                // max |wdiag| as positive-float bits
__device__ unsigned g_barcnt;
__device__ unsigned g_cnt[NTILES];              // per-column-tile GEMM completion
__device__ unsigned g_asplit[NPREP_A];          // per-m-tile A split done
__device__ unsigned g_usplit[NTILES];           // per-n-tile U split done
__device__ unsigned g_chkcnt;                   // W-check slices done (16)

// ---------------- init -------------------------------------------------------
__global__ void k_init() {
    int t = threadIdx.x;
    if (t == 0) { g_flag = 1; g_maxw_bits = 0u; g_barcnt = 0u; g_chkcnt = 0u; }
    for (int i = t; i < NPREP_A; i += blockDim.x) g_asplit[i] = 0u;
    if (t < NTILES) { g_usplit[t] = 0u; g_cnt[t] = 0u; }
}

// ---------------- mma/ldsm/cp.async helpers ----------------------------------
__device__ __forceinline__ void ldsm4(unsigned& r0, unsigned& r1,
                                      unsigned& r2, unsigned& r3, unsigned addr) {
    asm volatile("ldmatrix.sync.aligned.m8n8.x4.shared.b16 {%0,%1,%2,%3},[%4];\n"
                 : "=r"(r0), "=r"(r1), "=r"(r2), "=r"(r3) : "r"(addr));
}
__device__ __forceinline__ void mma_f16(float* c, const unsigned* a, const unsigned* b) {
    asm volatile(
        "mma.sync.aligned.m16n8k16.row.col.f32.f16.f16.f32 "
        "{%0,%1,%2,%3},{%4,%5,%6,%7},{%8,%9},{%0,%1,%2,%3};\n"
        : "+f"(c[0]), "+f"(c[1]), "+f"(c[2]), "+f"(c[3])
        : "r"(a[0]), "r"(a[1]), "r"(a[2]), "r"(a[3]), "r"(b[0]), "r"(b[1]));
}
__device__ __forceinline__ void cp16(unsigned dst, const void* src) {
    asm volatile("cp.async.cg.shared.global [%0], [%1], 16;\n" :: "r"(dst), "l"(src) : "memory");
}
__device__ __forceinline__ void cp_commit() {
    asm volatile("cp.async.commit_group;\n" ::: "memory");
}
template<int N> __device__ __forceinline__ void cp_wait() {
    asm volatile("cp.async.wait_group %0;\n" :: "n"(N) : "memory");
}
__device__ __forceinline__ void cvt_store4(__half* dst, float4 v) {
    __half h[4];
    h[0] = __float2half_rn(v.x); h[1] = __float2half_rn(v.y);
    h[2] = __float2half_rn(v.z); h[3] = __float2half_rn(v.w);
    *reinterpret_cast<uint2*>(dst) =
        make_uint2((unsigned)__half_as_ushort(h[0]) | ((unsigned)__half_as_ushort(h[1]) << 16),
                   (unsigned)__half_as_ushort(h[2]) | ((unsigned)__half_as_ushort(h[3]) << 16));
}

// GEMM geometry (R12/R15 best): CTA 128x128, 8 warps (2m x 4n), warp 64x32,
// BK=32 (two k16 subs), 3-stage cp.async pipeline, occ 2.
#define SMS 24                                   // smem row stride in fp16 elems
#define SUB_BYTES (128*SMS*2)                    // 6144 B per tensor per k16 sub
#define STG_BYTES (4*SUB_BYTES)                  // A0,A1,B0,B1 = 24576 B
#define NSTG 3
#define SMEM_TOTAL (NSTG*STG_BYTES)              // 73728 B; x2 CTAs = 144 KB/SM
#define NIT (EMB_/32)                            // 16 stages

// Mega kernel: [0,250) A-split | [250,258) U-split | [258,274) W-check |
//              [274,2274) GEMM | [2274,2402) truncated recurrence.
__global__ void __launch_bounds__(256, 2)
k_mega(const float* __restrict__ emb, const float* __restrict__ U,
       const float* __restrict__ W, const int* __restrict__ ids,
       const float* __restrict__ Wb) {
    extern __shared__ __align__(16) char smem_dyn[];
    const int bid = blockIdx.x;
    const int tid = threadIdx.x;

    if (bid < NPREP_A) {
        // ---------- A split: m-tile bid, 128 rows x 512 = 16384 float4 ----------
        const int p = bid;
        const float4* src = reinterpret_cast<const float4*>(emb) + (size_t)p * 16384;
        __half* dst = g_Ah + (size_t)p * 65536;
#pragma unroll 4
        for (int i = tid; i < 16384; i += 256)
            cvt_store4(dst + 4*(size_t)i, __ldg(src + i));
        __threadfence();
        __syncthreads();
        if (tid == 0) atomicExch(&g_asplit[p], 1u);

    } else if (bid < NPREP_A + NPREP_U) {
        // ---------- U split: n-tile, 128 rows x 512 = 16384 float4 ----------
        const int p = bid - NPREP_A;
        const float4* src = reinterpret_cast<const float4*>(U) + (size_t)p * 16384;
        __half* dst = g_Bh + (size_t)p * 65536;
#pragma unroll 4
        for (int i = tid; i < 16384; i += 256)
            cvt_store4(dst + 4*(size_t)i, __ldg(src + i));
        __threadfence();
        __syncthreads();
        if (tid == 0) atomicExch(&g_usplit[p], 1u);

    } else if (bid < NPREP) {
        // ---------- W check: 64 rows per CTA ----------
        const int c = bid - NPREP_A - NPREP_U;      // 0..15
        for (int row = c * 64; row < c * 64 + 64; ++row) {
            float4 v = __ldg(reinterpret_cast<const float4*>(W + (size_t)row * HID_) + tid);
            float vv[4] = {v.x, v.y, v.z, v.w};
#pragma unroll
            for (int p = 0; p < 4; p++) {
                int col = tid * 4 + p;
                if (col == row) {
                    g_wdiag[row] = vv[p];
                    atomicMax(&g_maxw_bits, (unsigned)__float_as_int(fabsf(vv[p])));
                } else if (vv[p] != 0.0f) g_flag = 0;
            }
        }
        __threadfence();
        __syncthreads();
        if (tid == 0) atomicAdd(&g_chkcnt, 1u);

    } else if (bid < NPREP + NGEMM) {
        // ================= GEMM part =================
        const unsigned sb = (unsigned)__cvta_generic_to_shared(smem_dyn);
        const int idx = bid - NPREP;
        const int mt = idx % MTILES, nt = idx / MTILES;   // m-fast raster
        const int m0 = mt * 128, n0 = nt * 128;

        // wait for this tile's operands to be split
        if (tid == 0) {
            while (atomicAdd(&g_asplit[mt], 0u) == 0u) __nanosleep(100);
            while (atomicAdd(&g_usplit[nt], 0u) == 0u) __nanosleep(100);
            __threadfence();
        }
        __syncthreads();

        const int r = tid >> 1, q = tid & 1;
        const unsigned doff = (unsigned)(r * SMS + q * 8) * 2;
        const __half* a_h = g_Ah + (size_t)(m0 + r) * EMB_ + q * 8;
        const __half* b_h = g_Bh + (size_t)(n0 + r) * EMB_ + q * 8;

        const int lane = tid & 31, warp = tid >> 5;
        const int wm = warp >> 2, wn = warp & 3;

        float acc[4][4][4];
#pragma unroll
        for (int i = 0; i < 4; i++)
#pragma unroll
            for (int j = 0; j < 4; j++)
#pragma unroll
                for (int k = 0; k < 4; k++) acc[i][j][k] = 0.0f;

        auto load_stage = [&](int s, int c) {
            unsigned base = sb + s * STG_BYTES + doff;
            const int k0 = c * 32;
            cp16(base,               a_h + k0);
            cp16(base + 1*SUB_BYTES, a_h + k0 + 16);
            cp16(base + 2*SUB_BYTES, b_h + k0);
            cp16(base + 3*SUB_BYTES, b_h + k0 + 16);
            cp_commit();
        };

        load_stage(0, 0);
        load_stage(1, 1);

        const int aoff0 = ((wm * 64 + (lane & 15)) * SMS + (lane >> 4) * 8) * 2;
        const int boff0 = ((wn * 32 + (lane & 7) + ((lane >> 4) << 3)) * SMS
                           + ((lane >> 3) & 1) * 8) * 2;

        for (int it = 0; it < NIT; ++it) {
            if (it < NIT-1) cp_wait<1>(); else cp_wait<0>();
            __syncthreads();
            if (it + 2 < NIT) load_stage((it + 2) % NSTG, it + 2);

            const unsigned stg = sb + (it % NSTG) * STG_BYTES;
#pragma unroll
            for (int sub = 0; sub < 2; ++sub) {
                const unsigned base = stg + sub * SUB_BYTES;
                unsigned Ah[4][4], Bh[4][2];
#pragma unroll
                for (int mi = 0; mi < 4; mi++) {
                    unsigned ad = base + aoff0 + mi * 16 * SMS * 2;
                    ldsm4(Ah[mi][0], Ah[mi][1], Ah[mi][2], Ah[mi][3], ad);
                }
#pragma unroll
                for (int p = 0; p < 2; p++) {
                    unsigned bd = base + 2*SUB_BYTES + boff0 + p * 16 * SMS * 2;
                    ldsm4(Bh[2*p][0], Bh[2*p][1], Bh[2*p+1][0], Bh[2*p+1][1], bd);
                }
#pragma unroll
                for (int mi = 0; mi < 4; mi++)
#pragma unroll
                    for (int ni = 0; ni < 4; ni++)
                        mma_f16(acc[mi][ni], Ah[mi], Bh[ni]);
            }
        }

        // epilogue: fp32 accumulators -> fp16 g_projh
#pragma unroll
        for (int mi = 0; mi < 4; mi++) {
            int mrow = m0 + wm * 64 + mi * 16 + (lane >> 2);
#pragma unroll
            for (int ni = 0; ni < 4; ni++) {
                int h = n0 + wn * 32 + ni * 8 + (lane & 3) * 2;
                *reinterpret_cast<__half2*>(&g_projh[(size_t)mrow * HID_ + h]) =
                    __floats2half2_rn(acc[mi][ni][0], acc[mi][ni][1]);
                *reinterpret_cast<__half2*>(&g_projh[(size_t)(mrow + 8) * HID_ + h]) =
                    __floats2half2_rn(acc[mi][ni][2], acc[mi][ni][3]);
            }
        }

        __threadfence();
        __syncthreads();
        if (tid == 0) atomicAdd(&g_cnt[nt], 1u);

    } else {
        // ========== truncated recurrence (diagonal fast path) ==========
        const int rb  = bid - NPREP - NGEMM;     // 0..127
        const int nt  = rb >> 4;                 // column tile 0..7
        const int sub = rb & 15;
        const int b   = sub * 16 + (tid >> 4);   // batch 0..255
        const int h8  = nt * 128 + (tid & 15) * 8;

        // wait for W-check and this column tile
        if (tid == 0) {
            while (atomicAdd(&g_chkcnt, 0u) < (unsigned)NPREP_W) __nanosleep(100);
            while (atomicAdd(&g_cnt[nt], 0u) < (unsigned)MTILES) __nanosleep(200);
            __threadfence();
        }
        __syncthreads();
        if (!g_flag) return;                     // fallback kernel handles it

        // safe truncation horizon: influence of h_{T-K} on h_T <= max|w|^K.
        const float mw = __int_as_float((int)g_maxw_bits);
        int K = T_;
        if (mw < 0.999f) {
            float l2 = log2f(fmaxf(mw, 1e-30f));
            K = (int)ceilf(-40.0f / l2);
            if (K < 1) K = 1;
            if (K > T_) K = T_;
        }
        const int t0 = T_ - K;

        float w[8], bb[8], hv[8];
#pragma unroll
        for (int p = 0; p < 8; p++) {
            w[p]  = g_wdiag[h8 + p];
            bb[p] = __ldg(&Wb[h8 + p]);
            hv[p] = 0.0f;
        }
        const int* idrow = ids + b * T_;
        for (int t = t0; t < T_; ++t) {
            int id = __ldg(&idrow[t]);
            uint4 raw = *reinterpret_cast<const uint4*>(&g_projh[(size_t)id * HID_ + h8]);
            unsigned rr[4] = {raw.x, raw.y, raw.z, raw.w};
#pragma unroll
            for (int p = 0; p < 4; p++) {
                float2 ux = __half22float2(*reinterpret_cast<const __half2*>(&rr[p]));
                hv[2*p]   = fmaxf(fmaf(hv[2*p],   w[2*p],   bb[2*p]   + ux.x), 0.f);
                hv[2*p+1] = fmaxf(fmaf(hv[2*p+1], w[2*p+1], bb[2*p+1] + ux.y), 0.f);
            }
        }
        float4* dst = reinterpret_cast<float4*>(&g_h[((size_t)b << 10) + h8]);
        dst[0] = make_float4(hv[0], hv[1], hv[2], hv[3]);
        dst[1] = make_float4(hv[4], hv[5], hv[6], hv[7]);
    }
}

// ---------------- recurrence, generic fallback (dormant in practice) --------
__global__ void k_rec_fb(const int* __restrict__ ids,
                         const float* __restrict__ W, const float* __restrict__ Wb) {
    if (g_flag) return;
    const int tid = blockIdx.x * blockDim.x + threadIdx.x;
    const int NT = gridDim.x * blockDim.x;
    for (int t = 0; t < T_; ++t) {
        const float* cur = (t & 1) ? g_h2 : g_h;
        float*       nxt = (t & 1) ? g_h  : g_h2;
        for (int o = tid; o < BH; o += NT) {
            int b = o >> 10, i = o & 1023;
            int id = ids[b * T_ + t];
            float s = Wb[i] + __half2float(g_projh[(size_t)id * HID_ + i]);
            if (t > 0) {
                const float* hr = cur + (b << 10);
                const float* wr = W + ((size_t)i << 10);
                for (int j = 0; j < HID_; ++j) s += hr[j] * wr[j];
            }
            nxt[o] = fmaxf(s, 0.0f);
        }
        __syncthreads();
        if (threadIdx.x == 0) {
            __threadfence();
            atomicAdd(&g_barcnt, 1u);
            while (atomicAdd(&g_barcnt, 0u) < 148u * (unsigned)(t + 1)) {}
        }
        __syncthreads();
    }
}

// ---------------- head: 1024 threads/block, 32 warps (8x latency parallelism)
__global__ void __launch_bounds__(1024)
k_head(const float* __restrict__ h1w, const float* __restrict__ h1b,
       const float* __restrict__ h2w, const float* __restrict__ h2b,
       float* __restrict__ out) {
    __shared__ float hs[HID_];
    __shared__ float zs[HEAD_];
    const int b = blockIdx.x, tid = threadIdx.x;
    hs[tid] = g_h[(size_t)b * HID_ + tid];
    __syncthreads();

    const int warp = tid >> 5, lane = tid & 31;
    for (int j = warp; j < HEAD_; j += 32) {
        float s = 0.0f;
        const float* w = h1w + (size_t)j * HID_;
#pragma unroll 8
        for (int k = lane; k < HID_; k += 32) s += hs[k] * __ldg(&w[k]);
#pragma unroll
        for (int o = 16; o; o >>= 1) s += __shfl_xor_sync(0xffffffffu, s, o);
        if (lane == 0) zs[j] = fmaxf(s + h1b[j], 0.0f);
    }
    __syncthreads();

    if (warp < NCLS_) {
        const int c = warp;
        float s = 0.0f;
        const float* w = h2w + (size_t)c * HEAD_;
        for (int j = lane; j < HEAD_; j += 32) s += zs[j] * __ldg(&w[j]);
#pragma unroll
        for (int o = 16; o; o >>= 1) s += __shfl_xor_sync(0xffffffffu, s, o);
        if (lane == 0) out[b * NCLS_ + c] = s + h2b[c];
    }
}

// ---------------- launcher ---------------------------------------------------
extern "C" void kernel_launch(void* const* d_in, const int* in_sizes, int n_in,
                              void* d_out, int out_size) {
    const int*   ids = (const int*)  d_in[0];
    const float* emb = (const float*)d_in[1];
    const float* U   = (const float*)d_in[2];
    const float* W   = (const float*)d_in[3];
    const float* Wb  = (const float*)d_in[4];
    const float* h1w = (const float*)d_in[5];
    const float* h1b = (const float*)d_in[6];
    const float* h2w = (const float*)d_in[7];
    const float* h2b = (const float*)d_in[8];
    float* out = (float*)d_out;

    cudaFuncSetAttribute(k_mega, cudaFuncAttributeMaxDynamicSharedMemorySize, SMEM_TOTAL);

    k_init<<<1, 256>>>();
    k_mega<<<NCTAS, 256, SMEM_TOTAL>>>(emb, U, W, ids, Wb);
    k_rec_fb<<<148, 256>>>(ids, W, Wb);
    k_head<<<B_, 1024>>>(h1w, h1b, h2w, h2b, out);
}